// round 1
// baseline (speedup 1.0000x reference)
#include <cuda_runtime.h>
#include <math.h>

#define HH 1024
#define LL 128
#define VOCAB 50257
#define ROWS_PER_BLK 8
#define NLOGITBLK ((VOCAB + ROWS_PER_BLK - 1) / ROWS_PER_BLK)   // 6283

// ---- scratch (no allocations allowed) ----
__device__ float g_scores[LL];
__device__ float g_attn[HH];
__device__ float g_gru_in[HH];
__device__ float g_hnew[HH];
__device__ float g_bmax[8192];
__device__ float g_bsum[8192];
__device__ float g_lse;

__device__ __forceinline__ float warp_sum(float v) {
#pragma unroll
    for (int o = 16; o > 0; o >>= 1) v += __shfl_down_sync(0xffffffffu, v, o);
    return v;
}

// K1: scores[l] = dot([q;h], attn_W[l]) + attn_b[l]   (128 blocks x 256 thr)
__global__ void k_scores(const int* __restrict__ ids,
                         const float* __restrict__ hidden,
                         const float* __restrict__ emb,
                         const float* __restrict__ attn_W,
                         const float* __restrict__ attn_b) {
    const int l = blockIdx.x, t = threadIdx.x;
    const size_t qbase = (size_t)ids[0] * HH;
    const float4* w  = (const float4*)(attn_W + (size_t)l * 2 * HH);
    const float4* q4 = (const float4*)(emb + qbase);
    const float4* h4 = (const float4*)hidden;
    float4 a = w[t],        b = q4[t];
    float acc = a.x*b.x + a.y*b.y + a.z*b.z + a.w*b.w;
    float4 c = w[t + 256],  d = h4[t];
    acc += c.x*d.x + c.y*d.y + c.z*d.z + c.w*d.w;
    __shared__ float sred[8];
    acc = warp_sum(acc);
    if ((t & 31) == 0) sred[t >> 5] = acc;
    __syncthreads();
    if (t == 0) {
        float s = 0.f;
#pragma unroll
        for (int i = 0; i < 8; i++) s += sred[i];
        g_scores[l] = s + attn_b[l];
    }
}

// K2: softmax over scores + attn_applied = w @ encoder_outputs  (4 blocks x 256 thr)
//     block 0 also writes attn_weights into d_out[VOCAB+HH ..]
__global__ void k_attn(const float* __restrict__ enc, float* __restrict__ out) {
    __shared__ float sw[LL];
    __shared__ float sm[2];
    const int t = threadIdx.x;
    if (t < LL) sw[t] = g_scores[t];
    __syncthreads();
    if (t == 0) {
        float m = -1e30f;
        for (int i = 0; i < LL; i++) m = fmaxf(m, sw[i]);
        float s = 0.f;
        for (int i = 0; i < LL; i++) s += expf(sw[i] - m);
        sm[0] = m; sm[1] = s;
    }
    __syncthreads();
    const float m = sm[0], inv = 1.f / sm[1];
    if (t < LL) sw[t] = expf(sw[t] - m) * inv;
    __syncthreads();
    if (blockIdx.x == 0 && t < LL) out[VOCAB + HH + t] = sw[t];
    const int hidx = blockIdx.x * 256 + t;   // 4*256 = 1024
    float acc = 0.f;
#pragma unroll 4
    for (int l = 0; l < LL; l++) acc += sw[l] * enc[(size_t)l * HH + hidx];
    g_attn[hidx] = acc;
}

// K3: gru_in = relu([q; attn_applied] @ comb_W.T + comb_b)  (128 blocks x 256 thr, warp/row)
__global__ void k_comb(const int* __restrict__ ids,
                       const float* __restrict__ emb,
                       const float* __restrict__ comb_W,
                       const float* __restrict__ comb_b) {
    __shared__ float4 sq[256];
    __shared__ float4 sa[256];
    const int t = threadIdx.x;
    const size_t qbase = (size_t)ids[0] * HH;
    sq[t] = ((const float4*)(emb + qbase))[t];
    sa[t] = ((const float4*)g_attn)[t];
    __syncthreads();
    const int w = t >> 5, lane = t & 31;
    const int j = blockIdx.x * 8 + w;
    const float4* wr = (const float4*)(comb_W + (size_t)j * 2 * HH);
    float acc = 0.f;
#pragma unroll
    for (int i = 0; i < 8; i++) {
        const int idx = lane + i * 32;
        float4 a = wr[idx],       b = sq[idx];
        acc += a.x*b.x + a.y*b.y + a.z*b.z + a.w*b.w;
        float4 c = wr[idx + 256], d = sa[idx];
        acc += c.x*d.x + c.y*d.y + c.z*d.z + c.w*d.w;
    }
    acc = warp_sum(acc);
    if (lane == 0) g_gru_in[j] = fmaxf(acc + comb_b[j], 0.f);
}

// K4: GRU cell, warp per output j: 6 dots of length H  (128 blocks x 256 thr)
__global__ void k_gru(const float* __restrict__ hidden,
                      const float* __restrict__ W_ih,
                      const float* __restrict__ W_hh,
                      const float* __restrict__ b_ih,
                      const float* __restrict__ b_hh,
                      float* __restrict__ out) {
    __shared__ float4 sg[256];
    __shared__ float4 sh[256];
    const int t = threadIdx.x;
    sg[t] = ((const float4*)g_gru_in)[t];
    sh[t] = ((const float4*)hidden)[t];
    __syncthreads();
    const int w = t >> 5, lane = t & 31;
    const int j = blockIdx.x * 8 + w;
    const float4* wir = (const float4*)(W_ih + (size_t)j * HH);
    const float4* wiz = (const float4*)(W_ih + (size_t)(j +     HH) * HH);
    const float4* win = (const float4*)(W_ih + (size_t)(j + 2 * HH) * HH);
    const float4* whr = (const float4*)(W_hh + (size_t)j * HH);
    const float4* whz = (const float4*)(W_hh + (size_t)(j +     HH) * HH);
    const float4* whn = (const float4*)(W_hh + (size_t)(j + 2 * HH) * HH);
    float a_ir = 0.f, a_iz = 0.f, a_in = 0.f, a_hr = 0.f, a_hz = 0.f, a_hn = 0.f;
#pragma unroll
    for (int i = 0; i < 8; i++) {
        const int idx = lane + i * 32;
        const float4 g = sg[idx], h = sh[idx];
        float4 v;
        v = wir[idx]; a_ir += v.x*g.x + v.y*g.y + v.z*g.z + v.w*g.w;
        v = wiz[idx]; a_iz += v.x*g.x + v.y*g.y + v.z*g.z + v.w*g.w;
        v = win[idx]; a_in += v.x*g.x + v.y*g.y + v.z*g.z + v.w*g.w;
        v = whr[idx]; a_hr += v.x*h.x + v.y*h.y + v.z*h.z + v.w*h.w;
        v = whz[idx]; a_hz += v.x*h.x + v.y*h.y + v.z*h.z + v.w*h.w;
        v = whn[idx]; a_hn += v.x*h.x + v.y*h.y + v.z*h.z + v.w*h.w;
    }
    a_ir = warp_sum(a_ir); a_iz = warp_sum(a_iz); a_in = warp_sum(a_in);
    a_hr = warp_sum(a_hr); a_hz = warp_sum(a_hz); a_hn = warp_sum(a_hn);
    if (lane == 0) {
        const float ir = a_ir + b_ih[j];
        const float iz = a_iz + b_ih[j + HH];
        const float inn = a_in + b_ih[j + 2 * HH];
        const float hr = a_hr + b_hh[j];
        const float hz = a_hz + b_hh[j + HH];
        const float hn = a_hn + b_hh[j + 2 * HH];
        const float r = 1.f / (1.f + expf(-(ir + hr)));
        const float z = 1.f / (1.f + expf(-(iz + hz)));
        const float n = tanhf(inn + r * hn);
        const float hnew = (1.f - z) * n + z * hidden[j];
        g_hnew[j] = hnew;
        out[VOCAB + j] = hnew;
    }
}

// K5: logits GEMV (the 206 MB read) + per-block (max, sumexp)  (6283 blocks x 256 thr)
__global__ void k_logits(const float* __restrict__ out_W,
                         const float* __restrict__ out_b,
                         float* __restrict__ out) {
    __shared__ float4 shn[256];
    __shared__ float slog[8];
    const int t = threadIdx.x;
    shn[t] = ((const float4*)g_hnew)[t];
    __syncthreads();
    const int w = t >> 5, lane = t & 31;
    const int v = blockIdx.x * 8 + w;
    float logit = -INFINITY;
    if (v < VOCAB) {
        const float4* wr = (const float4*)(out_W + (size_t)v * HH);
        float acc = 0.f;
#pragma unroll
        for (int i = 0; i < 8; i++) {
            const int idx = lane + i * 32;
            const float4 a = wr[idx], b = shn[idx];
            acc += a.x*b.x + a.y*b.y + a.z*b.z + a.w*b.w;
        }
        acc = warp_sum(acc);
        if (lane == 0) {
            logit = acc + out_b[v];
            out[v] = logit;
        }
    }
    if (lane == 0) slog[w] = logit;
    __syncthreads();
    if (t == 0) {
        float m = -INFINITY;
#pragma unroll
        for (int i = 0; i < 8; i++) m = fmaxf(m, slog[i]);
        float s = 0.f;
#pragma unroll
        for (int i = 0; i < 8; i++)
            if (slog[i] > -INFINITY) s += expf(slog[i] - m);
        g_bmax[blockIdx.x] = m;
        g_bsum[blockIdx.x] = s;
    }
}

// K6: combine block-local (max, sumexp) into global LSE  (1 block x 256 thr)
__global__ void k_lse() {
    __shared__ float sred[256];
    const int t = threadIdx.x;
    float m = -INFINITY;
    for (int i = t; i < NLOGITBLK; i += 256) m = fmaxf(m, g_bmax[i]);
    sred[t] = m;
    __syncthreads();
    for (int o = 128; o > 0; o >>= 1) {
        if (t < o) sred[t] = fmaxf(sred[t], sred[t + o]);
        __syncthreads();
    }
    const float M = sred[0];
    __syncthreads();
    float s = 0.f;
    for (int i = t; i < NLOGITBLK; i += 256) s += g_bsum[i] * expf(g_bmax[i] - M);
    sred[t] = s;
    __syncthreads();
    for (int o = 128; o > 0; o >>= 1) {
        if (t < o) sred[t] += sred[t + o];
        __syncthreads();
    }
    if (t == 0) g_lse = M + logf(sred[0]);
}

// K7: log_probs = logits - lse
__global__ void k_sub(float* __restrict__ out) {
    const int i = blockIdx.x * 256 + threadIdx.x;
    if (i < VOCAB) out[i] -= g_lse;
}

extern "C" void kernel_launch(void* const* d_in, const int* in_sizes, int n_in,
                              void* d_out, int out_size) {
    const int*   ids    = (const int*)  d_in[0];
    const float* hidden = (const float*)d_in[1];
    const float* enc    = (const float*)d_in[2];
    const float* emb    = (const float*)d_in[3];
    const float* attn_W = (const float*)d_in[4];
    const float* attn_b = (const float*)d_in[5];
    const float* comb_W = (const float*)d_in[6];
    const float* comb_b = (const float*)d_in[7];
    const float* W_ih   = (const float*)d_in[8];
    const float* W_hh   = (const float*)d_in[9];
    const float* b_ih   = (const float*)d_in[10];
    const float* b_hh   = (const float*)d_in[11];
    const float* out_W  = (const float*)d_in[12];
    const float* out_b  = (const float*)d_in[13];
    float* out = (float*)d_out;

    k_scores<<<LL, 256>>>(ids, hidden, emb, attn_W, attn_b);
    k_attn<<<4, 256>>>(enc, out);
    k_comb<<<HH / ROWS_PER_BLK, 256>>>(ids, emb, comb_W, comb_b);
    k_gru<<<HH / ROWS_PER_BLK, 256>>>(hidden, W_ih, W_hh, b_ih, b_hh, out);
    k_logits<<<NLOGITBLK, 256>>>(out_W, out_b, out);
    k_lse<<<1, 256>>>();
    k_sub<<<(VOCAB + 255) / 256, 256>>>(out);
}

// round 2
// speedup vs baseline: 1.2704x; 1.2704x over previous
#include <cuda_runtime.h>
#include <math.h>

#define HH 1024
#define LL 128
#define VOCAB 50257

// ---------------- device scratch (no allocations allowed) ----------------
__device__ float g_scores[LL];
__device__ float g_attn[HH];
__device__ float g_gru_in[HH];
__device__ float g_hnew[HH];
__device__ float g_ghr[HH], g_ghz[HH], g_ghn[HH];
__device__ float g_bmax[1024], g_bsum[1024];
__device__ float g_lse;
__device__ unsigned g_arrive = 0;
__device__ unsigned g_gen = 0;

__device__ __forceinline__ float warp_sum(float v) {
#pragma unroll
    for (int o = 16; o > 0; o >>= 1) v += __shfl_down_sync(0xffffffffu, v, o);
    return v;
}

// sense-reversing software grid barrier (all blocks co-resident: grid = #SMs)
__device__ __forceinline__ void grid_bar(unsigned nb) {
    __syncthreads();
    if (threadIdx.x == 0) {
        __threadfence();
        unsigned gen = *(volatile unsigned*)&g_gen;
        if (atomicAdd(&g_arrive, 1u) == nb - 1u) {
            *(volatile unsigned*)&g_arrive = 0u;
            __threadfence();
            *(volatile unsigned*)&g_gen = gen + 1u;
        } else {
            while (*(volatile unsigned*)&g_gen == gen) {}
        }
        __threadfence();
    }
    __syncthreads();
}

__device__ __forceinline__ void lse_combine(float& M, float& S, float m2, float s2) {
    if (m2 > M) { S = S * expf(M - m2) + s2; M = m2; }
    else        { S += s2 * expf(m2 - M); }
}

__global__ void __launch_bounds__(1024, 1)
fused_decoder(const int* __restrict__ ids,
              const float* __restrict__ hidden,
              const float* __restrict__ enc,
              const float* __restrict__ emb,
              const float* __restrict__ attn_W,
              const float* __restrict__ attn_b,
              const float* __restrict__ comb_W,
              const float* __restrict__ comb_b,
              const float* __restrict__ W_ih,
              const float* __restrict__ W_hh,
              const float* __restrict__ b_ih,
              const float* __restrict__ b_hh,
              const float* __restrict__ out_W,
              const float* __restrict__ out_b,
              float* __restrict__ out) {
    const unsigned nb = gridDim.x;
    const int t = threadIdx.x, wid = t >> 5, lane = t & 31, bid = blockIdx.x;
    const int task = wid * (int)nb + bid;   // warp-major: spreads tasks across SMs
    const int gw   = bid * 32 + wid;        // block-major: row locality for logits
    const int totW = (int)nb * 32;

    __shared__ float s_red[1024];
    __shared__ float s_w[LL];
    __shared__ float s_m[2];
    __shared__ float s_bm[32], s_bs[32];

    const size_t qb = (size_t)ids[0] * HH;
    const float4* q4 = (const float4*)(emb + qb);
    const float4* h4 = (const float4*)hidden;

    // ---------------- Phase 0: gh = W_hh @ h (+bias), and attention scores ----
    if (task < HH) {
        const int j = task;
        const float4* wr = (const float4*)(W_hh + (size_t)j * HH);
        const float4* wz = (const float4*)(W_hh + (size_t)(j + HH) * HH);
        const float4* wn = (const float4*)(W_hh + (size_t)(j + 2 * HH) * HH);
        float ar = 0.f, az = 0.f, an = 0.f;
#pragma unroll
        for (int i = 0; i < 8; i++) {
            const int idx = lane + 32 * i;
            const float4 hv = h4[idx];
            float4 v;
            v = wr[idx]; ar += v.x*hv.x + v.y*hv.y + v.z*hv.z + v.w*hv.w;
            v = wz[idx]; az += v.x*hv.x + v.y*hv.y + v.z*hv.z + v.w*hv.w;
            v = wn[idx]; an += v.x*hv.x + v.y*hv.y + v.z*hv.z + v.w*hv.w;
        }
        ar = warp_sum(ar); az = warp_sum(az); an = warp_sum(an);
        if (lane == 0) {
            g_ghr[j] = ar + b_hh[j];
            g_ghz[j] = az + b_hh[j + HH];
            g_ghn[j] = an + b_hh[j + 2 * HH];
        }
    } else if (task < HH + LL) {
        const int l = task - HH;
        const float4* w = (const float4*)(attn_W + (size_t)l * 2 * HH);
        float acc = 0.f;
#pragma unroll
        for (int i = 0; i < 8; i++) {
            const int idx = lane + 32 * i;
            float4 a = w[idx],       b = q4[idx];
            acc += a.x*b.x + a.y*b.y + a.z*b.z + a.w*b.w;
            float4 c = w[idx + 256], d = h4[idx];
            acc += c.x*d.x + c.y*d.y + c.z*d.z + c.w*d.w;
        }
        acc = warp_sum(acc);
        if (lane == 0) g_scores[l] = acc + attn_b[l];
    }
    grid_bar(nb);

    // ---------------- Phase 1: softmax + attn_applied (blocks 0..7) ----------
    if (bid < 8) {
        float sc = (t < LL) ? g_scores[t] : -INFINITY;
        if (t < LL) {
            float v = sc;
#pragma unroll
            for (int o = 16; o > 0; o >>= 1) v = fmaxf(v, __shfl_down_sync(0xffffffffu, v, o));
            if (lane == 0) s_bm[wid] = v;
        }
        __syncthreads();
        if (t == 0) s_m[0] = fmaxf(fmaxf(s_bm[0], s_bm[1]), fmaxf(s_bm[2], s_bm[3]));
        __syncthreads();
        float e = 0.f;
        if (t < LL) {
            e = expf(sc - s_m[0]);
            float v = warp_sum(e);
            if (lane == 0) s_bs[wid] = v;
        }
        __syncthreads();
        if (t == 0) s_m[1] = 1.f / (s_bs[0] + s_bs[1] + s_bs[2] + s_bs[3]);
        __syncthreads();
        if (t < LL) {
            s_w[t] = e * s_m[1];
            if (bid == 0) out[VOCAB + HH + t] = s_w[t];
        }
        __syncthreads();
        const int col = t & 127, lg = t >> 7;
        const int colg = bid * 128 + col;
        float acc = 0.f;
#pragma unroll
        for (int k = 0; k < 16; k++) {
            const int l = lg * 16 + k;
            acc += s_w[l] * enc[(size_t)l * HH + colg];
        }
        s_red[t] = acc;
        __syncthreads();
        if (t < 128) {
            float a = 0.f;
#pragma unroll
            for (int k = 0; k < 8; k++) a += s_red[t + 128 * k];
            g_attn[colg] = a;
        }
    }
    grid_bar(nb);

    // ---------------- Phase 2: gru_in = relu([q; attn] @ comb_W.T + b) -------
    if (task < HH) {
        const int j = task;
        const float4* wr = (const float4*)(comb_W + (size_t)j * 2 * HH);
        const float4* a4 = (const float4*)g_attn;
        float acc = 0.f;
#pragma unroll
        for (int i = 0; i < 8; i++) {
            const int idx = lane + 32 * i;
            float4 a = wr[idx],       b = q4[idx];
            acc += a.x*b.x + a.y*b.y + a.z*b.z + a.w*b.w;
            float4 c = wr[idx + 256], d = a4[idx];
            acc += c.x*d.x + c.y*d.y + c.z*d.z + c.w*d.w;
        }
        acc = warp_sum(acc);
        if (lane == 0) g_gru_in[j] = fmaxf(acc + comb_b[j], 0.f);
    }
    grid_bar(nb);

    // ---------------- Phase 3: gi = W_ih @ gru_in, + GRU gate math -----------
    if (task < HH) {
        const int j = task;
        const float4* wr = (const float4*)(W_ih + (size_t)j * HH);
        const float4* wz = (const float4*)(W_ih + (size_t)(j + HH) * HH);
        const float4* wn = (const float4*)(W_ih + (size_t)(j + 2 * HH) * HH);
        const float4* g4 = (const float4*)g_gru_in;
        float ar = 0.f, az = 0.f, an = 0.f;
#pragma unroll
        for (int i = 0; i < 8; i++) {
            const int idx = lane + 32 * i;
            const float4 gv = g4[idx];
            float4 v;
            v = wr[idx]; ar += v.x*gv.x + v.y*gv.y + v.z*gv.z + v.w*gv.w;
            v = wz[idx]; az += v.x*gv.x + v.y*gv.y + v.z*gv.z + v.w*gv.w;
            v = wn[idx]; an += v.x*gv.x + v.y*gv.y + v.z*gv.z + v.w*gv.w;
        }
        ar = warp_sum(ar); az = warp_sum(az); an = warp_sum(an);
        if (lane == 0) {
            const float ir  = ar + b_ih[j];
            const float iz  = az + b_ih[j + HH];
            const float inn = an + b_ih[j + 2 * HH];
            const float r = 1.f / (1.f + expf(-(ir + g_ghr[j])));
            const float z = 1.f / (1.f + expf(-(iz + g_ghz[j])));
            const float n = tanhf(inn + r * g_ghn[j]);
            const float hn = (1.f - z) * n + z * hidden[j];
            g_hnew[j] = hn;
            out[VOCAB + j] = hn;
        }
    }
    grid_bar(nb);

    // ---------------- Phase 5: logits GEMV (206 MB) + online (max,sumexp) ----
    {
        float4 hv[8];
#pragma unroll
        for (int i = 0; i < 8; i++) hv[i] = ((const float4*)g_hnew)[lane + 32 * i];
        float m = -INFINITY, s = 0.f;
        for (int r = gw; r < VOCAB; r += totW) {
            const float4* wr = (const float4*)(out_W + (size_t)r * HH);
            float acc = 0.f;
#pragma unroll
            for (int i = 0; i < 8; i++) {
                const float4 a = wr[lane + 32 * i];
                acc += a.x*hv[i].x + a.y*hv[i].y + a.z*hv[i].z + a.w*hv[i].w;
            }
            acc = warp_sum(acc);
            if (lane == 0) {
                const float lg = acc + out_b[r];
                out[r] = lg;
                lse_combine(m, s, lg, 1.f);
            }
        }
        if (lane == 0) { s_bm[wid] = m; s_bs[wid] = s; }
        __syncthreads();
        if (t == 0) {
            float M = -INFINITY, S = 0.f;
#pragma unroll
            for (int k = 0; k < 32; k++) lse_combine(M, S, s_bm[k], s_bs[k]);
            g_bmax[bid] = M; g_bsum[bid] = S;
        }
    }
    grid_bar(nb);

    // ---------------- Phase 6: global LSE ------------------------------------
    if (bid == 0 && wid == 0) {
        float M = -INFINITY, S = 0.f;
        for (int i = lane; i < (int)nb; i += 32) lse_combine(M, S, g_bmax[i], g_bsum[i]);
#pragma unroll
        for (int o = 16; o > 0; o >>= 1) {
            float m2 = __shfl_down_sync(0xffffffffu, M, o);
            float s2 = __shfl_down_sync(0xffffffffu, S, o);
            lse_combine(M, S, m2, s2);
        }
        if (lane == 0) g_lse = M + logf(S);
    }
    grid_bar(nb);

    // ---------------- Phase 7: log_probs = logits - lse ----------------------
    {
        const float lse = g_lse;
        for (int i = bid * 1024 + t; i < VOCAB; i += (int)nb * 1024) out[i] -= lse;
    }
}

extern "C" void kernel_launch(void* const* d_in, const int* in_sizes, int n_in,
                              void* d_out, int out_size) {
    const int*   ids    = (const int*)  d_in[0];
    const float* hidden = (const float*)d_in[1];
    const float* enc    = (const float*)d_in[2];
    const float* emb    = (const float*)d_in[3];
    const float* attn_W = (const float*)d_in[4];
    const float* attn_b = (const float*)d_in[5];
    const float* comb_W = (const float*)d_in[6];
    const float* comb_b = (const float*)d_in[7];
    const float* W_ih   = (const float*)d_in[8];
    const float* W_hh   = (const float*)d_in[9];
    const float* b_ih   = (const float*)d_in[10];
    const float* b_hh   = (const float*)d_in[11];
    const float* out_W  = (const float*)d_in[12];
    const float* out_b  = (const float*)d_in[13];
    float* out = (float*)d_out;

    int dev = 0, nsm = 148;
    cudaGetDevice(&dev);
    cudaDeviceGetAttribute(&nsm, cudaDevAttrMultiProcessorCount, dev);

    fused_decoder<<<nsm, 1024>>>(ids, hidden, enc, emb, attn_W, attn_b,
                                 comb_W, comb_b, W_ih, W_hh, b_ih, b_hh,
                                 out_W, out_b, out);
}